// round 9
// baseline (speedup 1.0000x reference)
#include <cuda_runtime.h>
#include <cstdint>

#define BB    1024
#define INF   4096
#define OUTF  4096
#define KF    64
#define TOPK  64

#define OTILE   8          // o-columns per CTA
#define PAD     9          // wt_s row pitch (floats)
#define NTHREADS 512
#define NWARPS  16

// 16MB score scratch: g_res[b*OUTF + o]
__device__ float g_res[(size_t)BB * OUTF];

// SMEM layout (dynamic):
//   wt_s  : [INF * PAD] floats            = 4096*9*4   = 147456 B
//   stage : [NWARPS*4 streams][128] f32   = 16*4*128*4 =  32768 B
//           per stream: [0..63] x values, [64..127] idx*PAD (as int)
#define SMEM_BYTES (INF * PAD * 4 + NWARPS * 4 * 128 * 4)

// ---------------------------------------------------------------------------
// Kernel 1: fused gather-matvec, SMEM-broadcast formulation.
// grid = OUTF/OTILE = 512 CTAs; each CTA: 8 o-columns x ALL 1024 b-rows.
// Warp layout: 4 b-streams (8 lanes each); lane&7 = o within tile.
// Each warp covers 64 consecutive b (16 per stream).
// ---------------------------------------------------------------------------
__global__ __launch_bounds__(NTHREADS, 1) void score_kernel(
    const float* __restrict__ x, const float* __restrict__ W,
    const float* __restrict__ bias, const int* __restrict__ pidx)
{
    extern __shared__ float smem[];
    float* wt_s = smem;                    // [INF*PAD]
    float* stgf = smem + INF * PAD;        // staging base

    const int tid  = threadIdx.x;
    const int w    = tid >> 5;
    const int lane = tid & 31;
    const int s    = lane >> 3;            // b-stream 0..3
    const int ol   = lane & 7;             // o within tile
    const int obase = blockIdx.x * OTILE;

    // ---- load W[o_tile, :] rows, store transposed wt_s[i*PAD + oo] ---------
    {
        const float4* W4 = (const float4*)W;
        for (int q = tid; q < OTILE * (INF / 4); q += NTHREADS) {
            int r  = q >> 10;               // row 0..7 (INF/4 = 1024)
            int c4 = q & 1023;              // float4 index within row
            float4 v = W4[(size_t)(obase + r) * (INF / 4) + c4];
            int i0 = c4 * 4;
            wt_s[(i0 + 0) * PAD + r] = v.x;
            wt_s[(i0 + 1) * PAD + r] = v.y;
            wt_s[(i0 + 2) * PAD + r] = v.z;
            wt_s[(i0 + 3) * PAD + r] = v.w;
        }
    }
    const float bias_o = bias[obase + ol];
    __syncthreads();

    // ---- main: each stream handles 16 b-rows ------------------------------
    float* st = stgf + (w * 4 + s) * 128;  // this stream's staging
    int*   sti = (int*)(st + 64);
    const int b0 = w * 64 + s * 16;

    float acc[16];

#pragma unroll 1
    for (int bb = 0; bb < 16; bb++) {
        const int b = b0 + bb;
        // stage x row + premultiplied idx row (8 lanes x 2 float4 / 2 int4)
        {
            const float4* xr = (const float4*)(x + b * KF);
            const int4*   ir = (const int4*)(pidx + b * KF);
            ((float4*)st)[ol]     = xr[ol];
            ((float4*)st)[8 + ol] = xr[8 + ol];
            int4 i0 = ir[ol];
            int4 i1 = ir[8 + ol];
            ((int4*)sti)[ol]     = make_int4(i0.x * PAD, i0.y * PAD, i0.z * PAD, i0.w * PAD);
            ((int4*)sti)[8 + ol] = make_int4(i1.x * PAD, i1.y * PAD, i1.z * PAD, i1.w * PAD);
        }
        __syncwarp();

        float a0 = 0.f, a1 = 0.f;   // split chains to halve FFMA dep latency
#pragma unroll
        for (int kq = 0; kq < KF / 4; kq++) {
            float4 xk = ((const float4*)st)[kq];
            int4   ik = ((const int4*)sti)[kq];
            a0 += xk.x * wt_s[ik.x + ol];
            a1 += xk.y * wt_s[ik.y + ol];
            a0 += xk.z * wt_s[ik.z + ol];
            a1 += xk.w * wt_s[ik.w + ol];
        }
        acc[bb] = a0 + a1;
        __syncwarp();   // protect staging before next bb overwrites
    }

    // ---- writeback (16 MB scratch) -----------------------------------------
#pragma unroll
    for (int bb = 0; bb < 16; bb++)
        g_res[(size_t)(b0 + bb) * OUTF + obase + ol] = acc[bb] + bias_o;
}

// ---------------------------------------------------------------------------
// float <-> order-preserving uint32 key
// ---------------------------------------------------------------------------
__device__ __forceinline__ unsigned f2key(float f) {
    unsigned u = __float_as_uint(f);
    return u ^ ((u & 0x80000000u) ? 0xFFFFFFFFu : 0x80000000u);
}
__device__ __forceinline__ float key2f(unsigned k) {
    unsigned u = k ^ ((k & 0x80000000u) ? 0x80000000u : 0xFFFFFFFFu);
    return __uint_as_float(u);
}

// ---------------------------------------------------------------------------
// Kernel 2: one block per batch row. Reads precomputed scores from g_res,
// exact top-64 via 64-bit-composite radix select + bitonic sort.
// (proven machinery from the 115us baseline, matvec removed)
// ---------------------------------------------------------------------------
__global__ __launch_bounds__(512) void topk_kernel(
    float* __restrict__ out, int write_idx)
{
    __shared__ unsigned hist[256];
    __shared__ unsigned long long s_prefix;
    __shared__ int s_target;
    __shared__ unsigned long long s_top[TOPK];
    __shared__ int s_cnt;

    const int b = blockIdx.x;
    const int tid = threadIdx.x;

    if (tid == 0) { s_prefix = 0ULL; s_target = TOPK; s_cnt = 0; }
    __syncthreads();

    // load 8 scores per thread (2x float4, coalesced)
    const float4* r4 = (const float4*)(g_res + (size_t)b * OUTF);
    float4 a0 = r4[tid];          // o = 4*tid .. 4*tid+3
    float4 a1 = r4[512 + tid];    // o = 2048 + 4*tid .. +3

    float v0[4] = {a0.x, a0.y, a0.z, a0.w};
    float v1[4] = {a1.x, a1.y, a1.z, a1.w};
    unsigned long long comp[8];
#pragma unroll
    for (int j = 0; j < 4; j++) {
        comp[j]     = ((unsigned long long)f2key(v0[j]) << 32) |
                      (unsigned)(OUTF - 1 - (4 * tid + j));
        comp[j + 4] = ((unsigned long long)f2key(v1[j]) << 32) |
                      (unsigned)(OUTF - 1 - (2048 + 4 * tid + j));
    }

    // ---- radix select: exact 64th-largest composite (8 passes of 8 bits) ---
    for (int p = 7; p >= 0; p--) {
        if (tid < 256) hist[tid] = 0;
        __syncthreads();
        const unsigned long long prefix_cur = s_prefix;
        const unsigned long long hi_mask = (p == 7) ? 0ULL : (~0ULL << ((p + 1) * 8));
#pragma unroll
        for (int j = 0; j < 8; j++) {
            if ((comp[j] & hi_mask) == prefix_cur)
                atomicAdd(&hist[(unsigned)(comp[j] >> (p * 8)) & 255u], 1u);
        }
        __syncthreads();
        for (int off = 1; off < 256; off <<= 1) {
            unsigned vv = 0;
            if (tid < 256 && tid + off < 256) vv = hist[tid + off];
            __syncthreads();
            if (tid < 256) hist[tid] += vv;
            __syncthreads();
        }
        int tgt = s_target;
        __syncthreads();
        if (tid < 256) {
            unsigned sv = hist[tid];
            unsigned sn = (tid < 255) ? hist[tid + 1] : 0u;
            if ((int)sv >= tgt && (int)sn < tgt) {
                s_prefix = prefix_cur | ((unsigned long long)tid << (p * 8));
                s_target = tgt - (int)sn;
            }
        }
        __syncthreads();
    }
    const unsigned long long T = s_prefix;

    // ---- collect winners ----------------------------------------------------
#pragma unroll
    for (int j = 0; j < 8; j++) {
        if (comp[j] >= T) {
            int pos = atomicAdd(&s_cnt, 1);
            if (pos < TOPK) s_top[pos] = comp[j];
        }
    }
    __syncthreads();

    // ---- bitonic sort descending (64) --------------------------------------
    for (int k2 = 2; k2 <= TOPK; k2 <<= 1) {
        for (int j = k2 >> 1; j > 0; j >>= 1) {
            if (tid < TOPK) {
                int ixj = tid ^ j;
                if (ixj > tid) {
                    bool desc = ((tid & k2) == 0);
                    unsigned long long aa = s_top[tid], bb2 = s_top[ixj];
                    if (desc ? (aa < bb2) : (aa > bb2)) {
                        s_top[tid] = bb2; s_top[ixj] = aa;
                    }
                }
            }
            __syncthreads();
        }
    }

    // ---- write: [B*64 vals][B*64 indices-as-float] -------------------------
    if (tid < TOPK) {
        unsigned long long c = s_top[tid];
        out[b * TOPK + tid] = key2f((unsigned)(c >> 32));
        if (write_idx)
            out[BB * TOPK + b * TOPK + tid] =
                (float)(OUTF - 1 - (int)(c & 0xFFFFFFFFu));
    }
}

// ---------------------------------------------------------------------------
extern "C" void kernel_launch(void* const* d_in, const int* in_sizes, int n_in,
                              void* d_out, int out_size) {
    const float* x    = (const float*)d_in[0];
    const float* w    = (const float*)d_in[1];
    const float* bias = (const float*)d_in[2];
    const int*   pidx = (const int*)d_in[3];
    (void)n_in;

    static int smem_set = 0;
    if (!smem_set) {
        cudaFuncSetAttribute(score_kernel,
                             cudaFuncAttributeMaxDynamicSharedMemorySize,
                             SMEM_BYTES);
        smem_set = 1;
    }

    score_kernel<<<OUTF / OTILE, NTHREADS, SMEM_BYTES>>>(x, w, bias, pidx);

    int write_idx = (out_size >= 2 * BB * TOPK) ? 1 : 0;
    topk_kernel<<<BB, 512>>>((float*)d_out, write_idx);
}

// round 13
// speedup vs baseline: 2.0435x; 2.0435x over previous
#include <cuda_runtime.h>
#include <cstdint>

#define BB    1024
#define INF   4096
#define OUTF  4096
#define KF    64
#define TOPK  64

// 64MB transposed-weight scratch: WT[i*OUTF + o] = W[o*INF + i]
__device__ float g_wt[(size_t)INF * OUTF];

// ---------------------------------------------------------------------------
// Kernel 1: tiled transpose W(OUT,IN) -> WT(IN,OUT), float4 both sides.
// 64x64 tile, 256 threads. W read with __ldcs (evict-first) so the streamed
// W bytes don't displace g_wt in L2.
// ---------------------------------------------------------------------------
__global__ __launch_bounds__(256) void transpose_kernel(const float* __restrict__ W) {
    __shared__ float tile[64][65];
    const int t  = threadIdx.x;
    const int tx = t & 15;        // float4 column within 64-wide i range
    const int ty = t >> 4;        // row group
    const int ibase = blockIdx.x * 64;
    const int obase = blockIdx.y * 64;

    const float4* W4 = (const float4*)W;
#pragma unroll
    for (int rr = 0; rr < 4; rr++) {
        int ol = ty + rr * 16;                       // o within tile
        float4 v = __ldcs(&W4[(size_t)(obase + ol) * (INF / 4) + (ibase >> 2) + tx]);
        tile[4 * tx + 0][ol] = v.x;
        tile[4 * tx + 1][ol] = v.y;
        tile[4 * tx + 2][ol] = v.z;
        tile[4 * tx + 3][ol] = v.w;
    }
    __syncthreads();

    float4* WT4 = (float4*)g_wt;
    const int oc = t & 15;        // float4 column within 64-wide o range
    const int iy = t >> 4;
#pragma unroll
    for (int rr = 0; rr < 4; rr++) {
        int il = iy + rr * 16;                       // i within tile
        float4 w;
        w.x = tile[il][4 * oc + 0];
        w.y = tile[il][4 * oc + 1];
        w.z = tile[il][4 * oc + 2];
        w.w = tile[il][4 * oc + 3];
        WT4[(size_t)(ibase + il) * (OUTF / 4) + (obase >> 2) + oc] = w;
    }
}

// ---------------------------------------------------------------------------
// float <-> order-preserving uint32 key
// ---------------------------------------------------------------------------
__device__ __forceinline__ unsigned f2key(float f) {
    unsigned u = __float_as_uint(f);
    return u ^ ((u & 0x80000000u) ? 0xFFFFFFFFu : 0x80000000u);
}
__device__ __forceinline__ float key2f(unsigned k) {
    unsigned u = k ^ ((k & 0x80000000u) ? 0x80000000u : 0xFFFFFFFFu);
    return __uint_as_float(u);
}

// ---------------------------------------------------------------------------
// Kernel 2: one block per batch row (PROVEN 95.3us / rel 1.4e-7 machinery).
//   - 512 threads, each accumulates 8 outputs (2x float4) in registers
//   - exact fp32 gather-matvec over 64 sparse columns (coalesced WT rows)
//   - exact top-64 via 64-bit-composite radix select + bitonic sort,
//     fully hidden behind the L2-bound gather.
// ---------------------------------------------------------------------------
__global__ __launch_bounds__(512) void router_kernel(
    const float* __restrict__ x, const float* __restrict__ bias,
    const int* __restrict__ pidx, float* __restrict__ out, int write_idx)
{
    __shared__ float sx[KF];
    __shared__ int   sc[KF];
    __shared__ unsigned hist[256];
    __shared__ unsigned long long s_prefix;
    __shared__ int s_target;
    __shared__ unsigned long long s_top[TOPK];
    __shared__ int s_cnt;

    const int b = blockIdx.x;
    const int tid = threadIdx.x;

    if (tid < KF) { sx[tid] = x[b * KF + tid]; sc[tid] = pidx[b * KF + tid]; }
    if (tid == 0) { s_prefix = 0ULL; s_target = TOPK; s_cnt = 0; }
    __syncthreads();

    // ---- gather matvec: 8 outputs per thread --------------------------------
    const float4* wt4 = (const float4*)g_wt;
    const float4* b4  = (const float4*)bias;
    float4 a0 = b4[tid];          // o = 4*tid .. 4*tid+3
    float4 a1 = b4[512 + tid];    // o = 2048 + 4*tid .. +3

#pragma unroll 8
    for (int k = 0; k < KF; k++) {
        float xv = sx[k];
        const float4* p = wt4 + (size_t)sc[k] * (OUTF / 4);
        float4 w0 = p[tid];
        float4 w1 = p[512 + tid];
        a0.x += xv * w0.x; a0.y += xv * w0.y; a0.z += xv * w0.z; a0.w += xv * w0.w;
        a1.x += xv * w1.x; a1.y += xv * w1.y; a1.z += xv * w1.z; a1.w += xv * w1.w;
    }

    // ---- build 64-bit composites -------------------------------------------
    float v0[4] = {a0.x, a0.y, a0.z, a0.w};
    float v1[4] = {a1.x, a1.y, a1.z, a1.w};
    unsigned long long comp[8];
#pragma unroll
    for (int j = 0; j < 4; j++) {
        comp[j]     = ((unsigned long long)f2key(v0[j]) << 32) |
                      (unsigned)(OUTF - 1 - (4 * tid + j));
        comp[j + 4] = ((unsigned long long)f2key(v1[j]) << 32) |
                      (unsigned)(OUTF - 1 - (2048 + 4 * tid + j));
    }

    // ---- radix select: exact 64th-largest composite (8 passes of 8 bits) ---
    for (int p = 7; p >= 0; p--) {
        if (tid < 256) hist[tid] = 0;
        __syncthreads();
        const unsigned long long prefix_cur = s_prefix;
        const unsigned long long hi_mask = (p == 7) ? 0ULL : (~0ULL << ((p + 1) * 8));
#pragma unroll
        for (int j = 0; j < 8; j++) {
            if ((comp[j] & hi_mask) == prefix_cur)
                atomicAdd(&hist[(unsigned)(comp[j] >> (p * 8)) & 255u], 1u);
        }
        __syncthreads();
        // inclusive suffix sum over hist
        for (int off = 1; off < 256; off <<= 1) {
            unsigned vv = 0;
            if (tid < 256 && tid + off < 256) vv = hist[tid + off];
            __syncthreads();
            if (tid < 256) hist[tid] += vv;
            __syncthreads();
        }
        int tgt = s_target;
        __syncthreads();
        if (tid < 256) {
            unsigned s  = hist[tid];
            unsigned sn = (tid < 255) ? hist[tid + 1] : 0u;
            if ((int)s >= tgt && (int)sn < tgt) {   // unique winner bin
                s_prefix = prefix_cur | ((unsigned long long)tid << (p * 8));
                s_target = tgt - (int)sn;
            }
        }
        __syncthreads();
    }
    const unsigned long long T = s_prefix;  // exact 64th-largest composite

    // ---- collect the 64 winners --------------------------------------------
#pragma unroll
    for (int j = 0; j < 8; j++) {
        if (comp[j] >= T) {
            int pos = atomicAdd(&s_cnt, 1);
            if (pos < TOPK) s_top[pos] = comp[j];
        }
    }
    __syncthreads();

    // ---- bitonic sort descending (64 elements) -----------------------------
    for (int k2 = 2; k2 <= TOPK; k2 <<= 1) {
        for (int j = k2 >> 1; j > 0; j >>= 1) {
            if (tid < TOPK) {
                int ixj = tid ^ j;
                if (ixj > tid) {
                    bool desc = ((tid & k2) == 0);
                    unsigned long long aa = s_top[tid], bb = s_top[ixj];
                    if (desc ? (aa < bb) : (aa > bb)) {
                        s_top[tid] = bb; s_top[ixj] = aa;
                    }
                }
            }
            __syncthreads();
        }
    }

    // ---- write: [B*64 vals][B*64 indices-as-float] -------------------------
    if (tid < TOPK) {
        unsigned long long c = s_top[tid];
        out[b * TOPK + tid] = key2f((unsigned)(c >> 32));
        if (write_idx)
            out[BB * TOPK + b * TOPK + tid] =
                (float)(OUTF - 1 - (int)(c & 0xFFFFFFFFu));
    }
}

// ---------------------------------------------------------------------------
extern "C" void kernel_launch(void* const* d_in, const int* in_sizes, int n_in,
                              void* d_out, int out_size) {
    const float* x    = (const float*)d_in[0];
    const float* w    = (const float*)d_in[1];
    const float* bias = (const float*)d_in[2];
    const int*   pidx = (const int*)d_in[3];
    (void)n_in;

    dim3 tg(INF / 64, OUTF / 64);
    transpose_kernel<<<tg, 256>>>(w);

    int write_idx = (out_size >= 2 * BB * TOPK) ? 1 : 0;
    router_kernel<<<BB, 512>>>(x, bias, pidx, (float*)d_out, write_idx);
}